// round 5
// baseline (speedup 1.0000x reference)
#include <cuda_runtime.h>
#include <math.h>

#define BATCH 4096
#define FEAT  4096
#define THREADS 512
#define WARPS_PER_BLOCK (THREADS / 32)
#define GRID (BATCH / WARPS_PER_BLOCK)   // 256 blocks, one row per warp

// Scratch accumulator + ticket (device globals; no allocation allowed).
__device__ float        g_acc    = 0.0f;
__device__ unsigned int g_ticket = 0u;

__global__ __launch_bounds__(THREADS, 3)
void fused_loss_kernel(const float* __restrict__ o1,
                       const float* __restrict__ o2,
                       const float* __restrict__ o3,
                       float* __restrict__ out) {
    const int tid  = threadIdx.x;
    const int lane = tid & 31;
    const int wid  = tid >> 5;

    // One row per warp: zero block barriers in the hot path.
    const int row = blockIdx.x * WARPS_PER_BLOCK + wid;
    const size_t base = (size_t)row * FEAT;
    const float4* __restrict__ a = reinterpret_cast<const float4*>(o1 + base);
    const float4* __restrict__ b = reinterpret_cast<const float4*>(o2 + base);
    const float4* __restrict__ c = reinterpret_cast<const float4*>(o3 + base);

    float s13 = 0.0f;
    float s12 = 0.0f;

    // 1024 float4 per row / 32 lanes = 32 iterations; unroll 4 -> 12 loads in flight.
#pragma unroll 4
    for (int it = 0; it < (FEAT / 4) / 32; ++it) {
        int i = lane + it * 32;
        float4 x = a[i];
        float4 y = b[i];
        float4 z = c[i];

        float d;
        d = x.x - z.x; s13 = fmaf(d, d, s13);
        d = x.y - z.y; s13 = fmaf(d, d, s13);
        d = x.z - z.z; s13 = fmaf(d, d, s13);
        d = x.w - z.w; s13 = fmaf(d, d, s13);

        d = x.x - y.x; s12 = fmaf(d, d, s12);
        d = x.y - y.y; s12 = fmaf(d, d, s12);
        d = x.z - y.z; s12 = fmaf(d, d, s12);
        d = x.w - y.w; s12 = fmaf(d, d, s12);
    }

    // Warp-local reduction only.
#pragma unroll
    for (int off = 16; off > 0; off >>= 1) {
        s13 += __shfl_down_sync(0xFFFFFFFFu, s13, off);
        s12 += __shfl_down_sync(0xFFFFFFFFu, s12, off);
    }

    __shared__ float s_block_sum;
    if (tid == 0) s_block_sum = 0.0f;
    __syncthreads();

    if (lane == 0) {
        float compare = 2.0f - sqrtf(s13) + sqrtf(s12);
        atomicAdd(&s_block_sum, fmaxf(0.0f, compare));   // smem atomic, 16/block
    }
    __syncthreads();

    // One global atomic per block; last block publishes the result.
    if (tid == 0) {
        atomicAdd(&g_acc, s_block_sum);
        __threadfence();
        unsigned int t = atomicAdd(&g_ticket, 1u);
        if (t == GRID - 1) {
            float total = atomicAdd(&g_acc, 0.0f);   // ordered read at L2
            out[0] = total * (float)BATCH;            // broadcast-sum over [B,B]
            g_acc = 0.0f;                             // reset for next replay
            __threadfence();
            g_ticket = 0u;
        }
    }
}

extern "C" void kernel_launch(void* const* d_in, const int* in_sizes, int n_in,
                              void* d_out, int out_size) {
    const float* o1 = (const float*)d_in[0];
    const float* o2 = (const float*)d_in[1];
    const float* o3 = (const float*)d_in[2];
    float* out = (float*)d_out;

    fused_loss_kernel<<<GRID, THREADS>>>(o1, o2, o3, out);
}

// round 6
// speedup vs baseline: 1.0070x; 1.0070x over previous
#include <cuda_runtime.h>
#include <math.h>

#define BATCH 4096
#define FEAT  4096
#define THREADS 256
#define GRID BATCH   // one row per block

// Scratch accumulator + ticket (device globals; no allocation allowed).
__device__ float        g_acc    = 0.0f;
__device__ unsigned int g_ticket = 0u;

__global__ __launch_bounds__(THREADS)
void fused_loss_kernel(const float* __restrict__ o1,
                       const float* __restrict__ o2,
                       const float* __restrict__ o3,
                       float* __restrict__ out) {
    const int row = blockIdx.x;
    const size_t base = (size_t)row * FEAT;
    const float4* __restrict__ a = reinterpret_cast<const float4*>(o1 + base);
    const float4* __restrict__ b = reinterpret_cast<const float4*>(o2 + base);
    const float4* __restrict__ c = reinterpret_cast<const float4*>(o3 + base);

    const int tid  = threadIdx.x;
    const int lane = tid & 31;
    const int wid  = tid >> 5;

    float s13 = 0.0f;
    float s12 = 0.0f;

    // 1024 float4 per row / 256 threads = 4 iterations, fully unrolled
    // (R0 config: 36 regs -> 7 CTAs/SM, 56 warps resident).
#pragma unroll
    for (int it = 0; it < (FEAT / 4) / THREADS; ++it) {
        int i = tid + it * THREADS;
        float4 x = a[i];
        float4 y = b[i];
        float4 z = c[i];

        float d;
        d = x.x - z.x; s13 = fmaf(d, d, s13);
        d = x.y - z.y; s13 = fmaf(d, d, s13);
        d = x.z - z.z; s13 = fmaf(d, d, s13);
        d = x.w - z.w; s13 = fmaf(d, d, s13);

        d = x.x - y.x; s12 = fmaf(d, d, s12);
        d = x.y - y.y; s12 = fmaf(d, d, s12);
        d = x.z - y.z; s12 = fmaf(d, d, s12);
        d = x.w - y.w; s12 = fmaf(d, d, s12);
    }

#pragma unroll
    for (int off = 16; off > 0; off >>= 1) {
        s13 += __shfl_down_sync(0xFFFFFFFFu, s13, off);
        s12 += __shfl_down_sync(0xFFFFFFFFu, s12, off);
    }

    __shared__ float sm13[THREADS / 32];
    __shared__ float sm12[THREADS / 32];
    if (lane == 0) { sm13[wid] = s13; sm12[wid] = s12; }
    __syncthreads();

    // One global atomic per block; last block to finish publishes the result.
    if (tid == 0) {
        float t13 = 0.0f, t12 = 0.0f;
#pragma unroll
        for (int w = 0; w < THREADS / 32; ++w) { t13 += sm13[w]; t12 += sm12[w]; }
        float compare = 2.0f - sqrtf(t13) + sqrtf(t12);
        float hinged = fmaxf(0.0f, compare);

        atomicAdd(&g_acc, hinged);
        __threadfence();
        unsigned int t = atomicAdd(&g_ticket, 1u);
        if (t == GRID - 1) {
            float total = atomicAdd(&g_acc, 0.0f);   // ordered read at L2
            out[0] = total * (float)BATCH;            // broadcast-sum over [B,B]
            g_acc = 0.0f;                             // reset for next replay
            __threadfence();
            g_ticket = 0u;
        }
    }
}

extern "C" void kernel_launch(void* const* d_in, const int* in_sizes, int n_in,
                              void* d_out, int out_size) {
    const float* o1 = (const float*)d_in[0];
    const float* o2 = (const float*)d_in[1];
    const float* o3 = (const float*)d_in[2];
    float* out = (float*)d_out;

    fused_loss_kernel<<<GRID, THREADS>>>(o1, o2, o3, out);
}

// round 7
// speedup vs baseline: 1.0596x; 1.0523x over previous
#include <cuda_runtime.h>
#include <math.h>

#define BATCH 4096
#define FEAT  4096
#define THREADS 512
#define GRID BATCH   // one row per block (R2 config: kernel measured 32.4us / 80% DRAM)

// Scratch accumulator + ticket (device globals; no allocation allowed).
__device__ float        g_acc    = 0.0f;
__device__ unsigned int g_ticket = 0u;

__global__ __launch_bounds__(THREADS)
void fused_loss_kernel(const float* __restrict__ o1,
                       const float* __restrict__ o2,
                       const float* __restrict__ o3,
                       float* __restrict__ out) {
    const int row = blockIdx.x;
    const size_t base = (size_t)row * FEAT;
    const float4* __restrict__ a = reinterpret_cast<const float4*>(o1 + base);
    const float4* __restrict__ b = reinterpret_cast<const float4*>(o2 + base);
    const float4* __restrict__ c = reinterpret_cast<const float4*>(o3 + base);

    const int tid  = threadIdx.x;
    const int lane = tid & 31;
    const int wid  = tid >> 5;

    float s13 = 0.0f;
    float s12 = 0.0f;

#pragma unroll
    for (int it = 0; it < (FEAT / 4) / THREADS; ++it) {
        int i = tid + it * THREADS;
        float4 x = a[i];
        float4 y = b[i];
        float4 z = c[i];

        float d;
        d = x.x - z.x; s13 = fmaf(d, d, s13);
        d = x.y - z.y; s13 = fmaf(d, d, s13);
        d = x.z - z.z; s13 = fmaf(d, d, s13);
        d = x.w - z.w; s13 = fmaf(d, d, s13);

        d = x.x - y.x; s12 = fmaf(d, d, s12);
        d = x.y - y.y; s12 = fmaf(d, d, s12);
        d = x.z - y.z; s12 = fmaf(d, d, s12);
        d = x.w - y.w; s12 = fmaf(d, d, s12);
    }

#pragma unroll
    for (int off = 16; off > 0; off >>= 1) {
        s13 += __shfl_down_sync(0xFFFFFFFFu, s13, off);
        s12 += __shfl_down_sync(0xFFFFFFFFu, s12, off);
    }

    __shared__ float sm13[THREADS / 32];
    __shared__ float sm12[THREADS / 32];
    if (lane == 0) { sm13[wid] = s13; sm12[wid] = s12; }
    __syncthreads();

    if (tid == 0) {
        float t13 = 0.0f, t12 = 0.0f;
#pragma unroll
        for (int w = 0; w < THREADS / 32; ++w) { t13 += sm13[w]; t12 += sm12[w]; }
        float compare = 2.0f - sqrtf(t13) + sqrtf(t12);
        float hinged = fmaxf(0.0f, compare);

        // Relaxed accumulator add (L2 atomic, no fence, no L1 flush).
        atomicAdd(&g_acc, hinged);

        // Release-semantics ticket add: orders the g_acc add before the ticket
        // WITHOUT a standalone __threadfence (which emits CCTL.IVALL / L1 flush).
        unsigned int old;
        asm volatile("atom.release.gpu.global.add.u32 %0, [%1], %2;"
                     : "=r"(old) : "l"(&g_ticket), "r"(1u) : "memory");

        if (old == GRID - 1) {
            // Single acquire in the whole grid: synchronizes with all
            // release-ticket adds, so every g_acc contribution is visible.
            float total;
            asm volatile("ld.acquire.gpu.global.f32 %0, [%1];"
                         : "=f"(total) : "l"(&g_acc) : "memory");
            out[0] = total * (float)BATCH;   // broadcast-sum over [B,B]
            // Reset scratch for the next graph replay (launch boundary orders this).
            g_acc = 0.0f;
            asm volatile("st.release.gpu.global.u32 [%0], %1;"
                         :: "l"(&g_ticket), "r"(0u) : "memory");
        }
    }
}

extern "C" void kernel_launch(void* const* d_in, const int* in_sizes, int n_in,
                              void* d_out, int out_size) {
    const float* o1 = (const float*)d_in[0];
    const float* o2 = (const float*)d_in[1];
    const float* o3 = (const float*)d_in[2];
    float* out = (float*)d_out;

    fused_loss_kernel<<<GRID, THREADS>>>(o1, o2, o3, out);
}